// round 4
// baseline (speedup 1.0000x reference)
#include <cuda_runtime.h>
#include <math.h>

#define MAX_NODES 50000
#define NPAD_CAP 51200
#define MAX_EDGES 800000
#define D 64
#define B 64
#define HL 128
#define SCAN_TILE 1024
#define POOL_CHUNK 1024
#define NBLOCKS 444
#define SMEM_FLOATS 16512   // wA4 4096 + wB4 4096 + rows 4096 + ts 4096 + 128

// ---------------- scratch (device globals; no allocation) ----------------
__device__ __align__(16) int g_counts[NPAD_CAP];
__device__ __align__(16) int g_offs[NPAD_CAP];
__device__ __align__(16) int g_cursor[NPAD_CAP];
__device__ int g_blocksums[64];
__device__ int g_elist[MAX_EDGES];
__device__ __align__(16) float g_h1[MAX_NODES * D];
__device__ __align__(16) float g_h2[MAX_NODES * D];
__device__ __align__(16) float g_sums[B * D];
__device__ float g_cntb[B];
__device__ volatile unsigned g_gen;
__device__ unsigned g_arrive;

// ---------------- software grid barrier (all blocks resident) ----------------
__device__ __forceinline__ void gbar() {
    __syncthreads();
    if (threadIdx.x == 0) {
        unsigned gen = g_gen;
        __threadfence();
        if (atomicAdd(&g_arrive, 1u) == gridDim.x - 1) {
            g_arrive = 0;
            __threadfence();
            g_gen = gen + 1;
        } else {
            while (g_gen == gen) __nanosleep(64);
        }
        __threadfence();
    }
    __syncthreads();
}

// ---------------- packed f32x2 helpers ----------------
__device__ __forceinline__ void ffma2(unsigned long long& acc,
                                      unsigned long long a, unsigned long long b) {
    asm("fma.rn.f32x2 %0, %1, %2, %3;" : "=l"(acc) : "l"(a), "l"(b), "l"(acc));
}
__device__ __forceinline__ float f32x2_sum(unsigned long long v) {
    float lo = __uint_as_float((unsigned)(v & 0xffffffffull));
    float hi = __uint_as_float((unsigned)(v >> 32));
    return lo + hi;
}

// ---------------- fused gather + GIN MLP (one layer) ----------------
// out[i] = relu(relu((xin[i] + sum_{j in N(i)} feat[j]) @ wA.T + bA) @ wB.T + bB)
__device__ void layer_phase(const float* __restrict__ feat,
                            const float* __restrict__ xin,
                            const float* __restrict__ wA, const float* __restrict__ bA,
                            const float* __restrict__ wB, const float* __restrict__ bB,
                            float* __restrict__ outbuf, int n, float* smem) {
    float4* wA4 = (float4*)smem;
    float4* wB4 = (float4*)(smem + 4096);
    float* rowsbuf = smem + 8192;
    float* tsbuf = smem + 12288;
    float* bAs = smem + 16384;
    float* bBs = smem + 16448;

    int tid = threadIdx.x, warp = tid >> 5, lane = tid & 31;
    for (int idx = tid; idx < 1024; idx += 256) {
        int j0 = idx & 31, k = (idx >> 5) * 2;
        wA4[idx] = make_float4(wA[j0 * 64 + k], wA[j0 * 64 + k + 1],
                               wA[(j0 + 32) * 64 + k], wA[(j0 + 32) * 64 + k + 1]);
        wB4[idx] = make_float4(wB[j0 * 64 + k], wB[j0 * 64 + k + 1],
                               wB[(j0 + 32) * 64 + k], wB[(j0 + 32) * 64 + k + 1]);
    }
    if (tid < 64) { bAs[tid] = bA[tid]; bBs[tid] = bB[tid]; }
    __syncthreads();

    float* rows = rowsbuf + warp * 512;
    float* ts = tsbuf + warp * 512;
    unsigned rows_a = (unsigned)__cvta_generic_to_shared(rows);
    unsigned ts_a = (unsigned)__cvta_generic_to_shared(ts);
    unsigned wA_a = (unsigned)__cvta_generic_to_shared(wA4);
    unsigned wB_a = (unsigned)__cvta_generic_to_shared(wB4);

    float bAj0 = bAs[lane], bAj1 = bAs[lane + 32];
    float bBj0 = bBs[lane], bBj1 = bBs[lane + 32];

    int ngroups = (n + 7) >> 3;
    int gw = blockIdx.x * 8 + warp;
    int gstride = gridDim.x * 8;

    for (int g = gw; g < ngroups; g += gstride) {
        int r0 = g * 8;
        // ---- gather 8 rows: xin[node] + sum of neighbor feat rows ----
        for (int i = 0; i < 8; i++) {
            int node = r0 + i;
            float2 r = make_float2(0.f, 0.f);
            if (node < n) {
                int start = __ldg(g_offs + node);
                int deg = __ldg(g_counts + node);
                float2 a0 = ((const float2*)(xin + (size_t)node * 64))[lane];
                float2 a1 = make_float2(0.f, 0.f), a2 = make_float2(0.f, 0.f);
                float2 a3 = make_float2(0.f, 0.f), a4 = make_float2(0.f, 0.f);
                float2 a5 = make_float2(0.f, 0.f), a6 = make_float2(0.f, 0.f);
                float2 a7 = make_float2(0.f, 0.f);
                int e = 0;
                for (; e + 7 < deg; e += 8) {
                    int s0 = __ldg(g_elist + start + e);
                    int s1 = __ldg(g_elist + start + e + 1);
                    int s2 = __ldg(g_elist + start + e + 2);
                    int s3 = __ldg(g_elist + start + e + 3);
                    int s4 = __ldg(g_elist + start + e + 4);
                    int s5 = __ldg(g_elist + start + e + 5);
                    int s6 = __ldg(g_elist + start + e + 6);
                    int s7 = __ldg(g_elist + start + e + 7);
                    float2 v0 = ((const float2*)(feat + (size_t)s0 * 64))[lane];
                    float2 v1 = ((const float2*)(feat + (size_t)s1 * 64))[lane];
                    float2 v2 = ((const float2*)(feat + (size_t)s2 * 64))[lane];
                    float2 v3 = ((const float2*)(feat + (size_t)s3 * 64))[lane];
                    float2 v4 = ((const float2*)(feat + (size_t)s4 * 64))[lane];
                    float2 v5 = ((const float2*)(feat + (size_t)s5 * 64))[lane];
                    float2 v6 = ((const float2*)(feat + (size_t)s6 * 64))[lane];
                    float2 v7 = ((const float2*)(feat + (size_t)s7 * 64))[lane];
                    a0.x += v0.x; a0.y += v0.y; a1.x += v1.x; a1.y += v1.y;
                    a2.x += v2.x; a2.y += v2.y; a3.x += v3.x; a3.y += v3.y;
                    a4.x += v4.x; a4.y += v4.y; a5.x += v5.x; a5.y += v5.y;
                    a6.x += v6.x; a6.y += v6.y; a7.x += v7.x; a7.y += v7.y;
                }
                if (e + 3 < deg) {
                    int s0 = __ldg(g_elist + start + e);
                    int s1 = __ldg(g_elist + start + e + 1);
                    int s2 = __ldg(g_elist + start + e + 2);
                    int s3 = __ldg(g_elist + start + e + 3);
                    float2 v0 = ((const float2*)(feat + (size_t)s0 * 64))[lane];
                    float2 v1 = ((const float2*)(feat + (size_t)s1 * 64))[lane];
                    float2 v2 = ((const float2*)(feat + (size_t)s2 * 64))[lane];
                    float2 v3 = ((const float2*)(feat + (size_t)s3 * 64))[lane];
                    a0.x += v0.x; a0.y += v0.y; a1.x += v1.x; a1.y += v1.y;
                    a2.x += v2.x; a2.y += v2.y; a3.x += v3.x; a3.y += v3.y;
                    e += 4;
                }
                for (; e < deg; e++) {
                    int s0 = __ldg(g_elist + start + e);
                    float2 v0 = ((const float2*)(feat + (size_t)s0 * 64))[lane];
                    a0.x += v0.x; a0.y += v0.y;
                }
                r.x = a0.x + a1.x + a2.x + a3.x + a4.x + a5.x + a6.x + a7.x;
                r.y = a0.y + a1.y + a2.y + a3.y + a4.y + a5.y + a6.y + a7.y;
            }
            ((float2*)(rows + i * 64))[lane] = r;
        }
        __syncwarp();

        // ---- phase 1: t = relu(rows @ wA.T + bA) ----
        unsigned long long acc[8][2];
#pragma unroll
        for (int i = 0; i < 8; i++) { acc[i][0] = 0ull; acc[i][1] = 0ull; }
#pragma unroll 4
        for (int k2 = 0; k2 < 32; k2++) {
            unsigned long long w0, w1;
            asm volatile("ld.shared.v2.u64 {%0,%1}, [%2];"
                         : "=l"(w0), "=l"(w1) : "r"(wA_a + (k2 * 32 + lane) * 16));
#pragma unroll
            for (int i = 0; i < 8; i++) {
                unsigned long long h2;
                asm volatile("ld.shared.b64 %0, [%1];"
                             : "=l"(h2) : "r"(rows_a + i * 256 + k2 * 8));
                ffma2(acc[i][0], h2, w0);
                ffma2(acc[i][1], h2, w1);
            }
        }
#pragma unroll
        for (int i = 0; i < 8; i++) {
            ts[i * 64 + lane] = fmaxf(f32x2_sum(acc[i][0]) + bAj0, 0.f);
            ts[i * 64 + lane + 32] = fmaxf(f32x2_sum(acc[i][1]) + bAj1, 0.f);
        }
        __syncwarp();

        // ---- phase 2: out = relu(t @ wB.T + bB) ----
#pragma unroll
        for (int i = 0; i < 8; i++) { acc[i][0] = 0ull; acc[i][1] = 0ull; }
#pragma unroll 4
        for (int k2 = 0; k2 < 32; k2++) {
            unsigned long long w0, w1;
            asm volatile("ld.shared.v2.u64 {%0,%1}, [%2];"
                         : "=l"(w0), "=l"(w1) : "r"(wB_a + (k2 * 32 + lane) * 16));
#pragma unroll
            for (int i = 0; i < 8; i++) {
                unsigned long long h2;
                asm volatile("ld.shared.b64 %0, [%1];"
                             : "=l"(h2) : "r"(ts_a + i * 256 + k2 * 8));
                ffma2(acc[i][0], h2, w0);
                ffma2(acc[i][1], h2, w1);
            }
        }
        int nr = min(8, n - r0);
        for (int i = 0; i < nr; i++) {
            outbuf[(size_t)(r0 + i) * 64 + lane] = fmaxf(f32x2_sum(acc[i][0]) + bBj0, 0.f);
            outbuf[(size_t)(r0 + i) * 64 + lane + 32] = fmaxf(f32x2_sum(acc[i][1]) + bBj1, 0.f);
        }
        __syncwarp();
    }
}

// ---------------- the megakernel ----------------
__global__ void __launch_bounds__(256, 3) mega_kernel(
        const float* __restrict__ x, const int* __restrict__ ei,
        const int* __restrict__ batch,
        const float* __restrict__ w1, const float* __restrict__ b1,
        const float* __restrict__ w2, const float* __restrict__ b2,
        const float* __restrict__ w3, const float* __restrict__ b3,
        const float* __restrict__ w4, const float* __restrict__ b4,
        const float* __restrict__ w_ih, const float* __restrict__ w_hh,
        const float* __restrict__ b_ih, const float* __restrict__ b_hh,
        const float* __restrict__ fc_w, const float* __restrict__ fc_b,
        const float* __restrict__ h0, const float* __restrict__ c0,
        float* __restrict__ out, int n_nodes, int n_edges, int npad, int nsb) {
    extern __shared__ float smem[];
    int tid = threadIdx.x, bid = blockIdx.x;
    int nb = gridDim.x;
    int gtid = bid * 256 + tid;
    int gthreads = nb * 256;
    int lane = tid & 31, warp = tid >> 5;

    // ---- P0: zero counts + pool accumulators ----
    for (int i = gtid; i < npad; i += gthreads) g_counts[i] = 0;
    if (bid == 0) {
        for (int i = tid; i < B * D; i += 256) g_sums[i] = 0.f;
        if (tid < B) g_cntb[tid] = 0.f;
    }
    gbar();

    // ---- P1: degree count ----
    for (int e = gtid; e < n_edges; e += gthreads)
        atomicAdd(&g_counts[__ldg(ei + n_edges + e)], 1);
    gbar();

    // ---- P2: per-tile scan (local exclusive + tile sum) ----
    if (bid < nsb) {
        int* wsum = (int*)smem;
        int idx = bid * SCAN_TILE + tid * 4;
        int4 v = *(const int4*)(g_counts + idx);
        int s = v.x + v.y + v.z + v.w;
        int incl = s;
#pragma unroll
        for (int off = 1; off < 32; off <<= 1) {
            int u = __shfl_up_sync(0xffffffffu, incl, off);
            if (lane >= off) incl += u;
        }
        if (lane == 31) wsum[warp] = incl;
        __syncthreads();
        if (warp == 0) {
            int ws = (lane < 8) ? wsum[lane] : 0;
#pragma unroll
            for (int off = 1; off < 8; off <<= 1) {
                int u = __shfl_up_sync(0xffffffffu, ws, off);
                if (lane >= off) ws += u;
            }
            if (lane < 8) wsum[lane] = ws;
        }
        __syncthreads();
        int wbase = warp ? wsum[warp - 1] : 0;
        int ebase = wbase + incl - s;
        int4 e;
        e.x = ebase; e.y = ebase + v.x; e.z = e.y + v.y; e.w = e.z + v.z;
        *(int4*)(g_offs + idx) = e;
        if (tid == 255) g_blocksums[bid] = wsum[7];
    }
    gbar();

    // ---- P3: add tile base (parallel reduce of preceding tile sums) ----
    if (bid < nsb) {
        int* part = (int*)smem;
        int v = (tid < bid) ? g_blocksums[tid] : 0;   // bid < 64
        if (tid < 64) {
#pragma unroll
            for (int off = 16; off; off >>= 1)
                v += __shfl_down_sync(0xffffffffu, v, off);
            if (lane == 0) part[warp] = v;
        }
        __syncthreads();
        int base = part[0] + part[1];
        int idx = bid * SCAN_TILE + tid * 4;
        int4 e = *(int4*)(g_offs + idx);
        e.x += base; e.y += base; e.z += base; e.w += base;
        *(int4*)(g_offs + idx) = e;
        *(int4*)(g_cursor + idx) = e;
    }
    gbar();

    // ---- P4: fill edge list (sorted by dst) ----
    for (int e = gtid; e < n_edges; e += gthreads) {
        int s = __ldg(ei + e);
        int d = __ldg(ei + n_edges + e);
        int p = atomicAdd(&g_cursor[d], 1);
        g_elist[p] = s;
    }
    gbar();

    // ---- P5: layer 1 (gather + MLP) ----
    layer_phase(x, x, w1, b1, w2, b2, g_h1, n_nodes, smem);
    gbar();

    // ---- P6: layer 2 ----
    layer_phase(g_h1, g_h1, w3, b3, w4, b4, g_h2, n_nodes, smem);
    gbar();

    // ---- P7: mean-pool over sorted batch ----
    {
        int d = tid & 63;
        int sub = tid >> 6;
        int nchunks = (n_nodes + POOL_CHUNK - 1) / POOL_CHUNK;
        for (int ch = bid; ch < nchunks; ch += nb) {
            int start = ch * POOL_CHUNK + sub;
            int end = min(ch * POOL_CHUNK + POOL_CHUNK, n_nodes);
            float acc = 0.f, c = 0.f;
            int cur = -1;
            for (int r = start; r < end; r += 4) {
                int b = __ldg(batch + r);
                if (b != cur) {
                    if (cur >= 0) {
                        atomicAdd(&g_sums[cur * 64 + d], acc);
                        if (d == 0) atomicAdd(&g_cntb[cur], c);
                    }
                    cur = b; acc = 0.f; c = 0.f;
                }
                acc += g_h2[(size_t)r * 64 + d];
                c += 1.f;
            }
            if (cur >= 0) {
                atomicAdd(&g_sums[cur * 64 + d], acc);
                if (d == 0) atomicAdd(&g_cntb[cur], c);
            }
        }
    }
    gbar();

    // ---- P8: gates + LSTM cell + FC + softmax (block b = batch b) ----
    if (bid < B) {
        int b = bid;
        float* ps = smem;           // 64
        float* h0s = smem + 64;     // 128
        float* gsm = smem + 192;    // 512
        float* h1s = smem + 704;    // 128
        if (tid < 64) ps[tid] = g_sums[b * 64 + tid] / fmaxf(g_cntb[b], 1.f);
        if (tid >= 64 && tid < 192) h0s[tid - 64] = h0[b * 128 + (tid - 64)];
        __syncthreads();
#pragma unroll
        for (int jj = 0; jj < 2; jj++) {
            int j = tid + jj * 256;
            float acc = b_ih[j] + b_hh[j];
            const float4* wi = (const float4*)(w_ih + (size_t)j * 64);
#pragma unroll
            for (int k4 = 0; k4 < 16; k4++) {
                float4 w = __ldg(wi + k4);
                acc += w.x * ps[k4 * 4] + w.y * ps[k4 * 4 + 1]
                     + w.z * ps[k4 * 4 + 2] + w.w * ps[k4 * 4 + 3];
            }
            const float4* wh = (const float4*)(w_hh + (size_t)j * 128);
#pragma unroll
            for (int k4 = 0; k4 < 32; k4++) {
                float4 w = __ldg(wh + k4);
                acc += w.x * h0s[k4 * 4] + w.y * h0s[k4 * 4 + 1]
                     + w.z * h0s[k4 * 4 + 2] + w.w * h0s[k4 * 4 + 3];
            }
            gsm[j] = acc;
        }
        __syncthreads();
        if (tid < 128) {
            float gi = gsm[tid], gf = gsm[128 + tid];
            float gg = gsm[256 + tid], go = gsm[384 + tid];
            float si = 1.f / (1.f + expf(-gi));
            float sf = 1.f / (1.f + expf(-gf));
            float so = 1.f / (1.f + expf(-go));
            float c1 = sf * c0[b * 128 + tid] + si * tanhf(gg);
            float h1v = so * tanhf(c1);
            out[B * 32 + b * 128 + tid] = h1v;
            out[B * 32 + B * 128 + b * 128 + tid] = c1;
            h1s[tid] = h1v;
        }
        __syncthreads();
        if (tid < 32) {
            float acc = fc_b[tid];
            const float4* fw = (const float4*)(fc_w + (size_t)tid * 128);
#pragma unroll
            for (int k4 = 0; k4 < 32; k4++) {
                float4 w = __ldg(fw + k4);
                acc += w.x * h1s[k4 * 4] + w.y * h1s[k4 * 4 + 1]
                     + w.z * h1s[k4 * 4 + 2] + w.w * h1s[k4 * 4 + 3];
            }
            float m = acc;
            for (int off = 16; off; off >>= 1)
                m = fmaxf(m, __shfl_xor_sync(0xffffffffu, m, off));
            float e = expf(acc - m);
            float s = e;
            for (int off = 16; off; off >>= 1)
                s += __shfl_xor_sync(0xffffffffu, s, off);
            out[b * 32 + tid] = e / s;
        }
    }
}

// ---------------- launch ----------------
extern "C" void kernel_launch(void* const* d_in, const int* in_sizes, int n_in,
                              void* d_out, int out_size) {
    const float* x     = (const float*)d_in[0];
    const int*   ei    = (const int*)d_in[1];
    const int*   batch = (const int*)d_in[2];
    const float* w1    = (const float*)d_in[3];
    const float* b1    = (const float*)d_in[4];
    const float* w2    = (const float*)d_in[5];
    const float* b2    = (const float*)d_in[6];
    const float* w3    = (const float*)d_in[7];
    const float* b3    = (const float*)d_in[8];
    const float* w4    = (const float*)d_in[9];
    const float* b4    = (const float*)d_in[10];
    const float* w_ih  = (const float*)d_in[11];
    const float* w_hh  = (const float*)d_in[12];
    const float* b_ih  = (const float*)d_in[13];
    const float* b_hh  = (const float*)d_in[14];
    const float* fc_w  = (const float*)d_in[15];
    const float* fc_b  = (const float*)d_in[16];
    const float* h0    = (const float*)d_in[17];
    const float* c0    = (const float*)d_in[18];
    float* out = (float*)d_out;

    int n_nodes = in_sizes[0] / 64;
    int n_edges = in_sizes[1] / 2;
    int npad = (n_nodes + SCAN_TILE - 1) & ~(SCAN_TILE - 1);
    int nsb = npad / SCAN_TILE;

    cudaFuncSetAttribute(mega_kernel, cudaFuncAttributeMaxDynamicSharedMemorySize,
                         SMEM_FLOATS * 4);

    mega_kernel<<<NBLOCKS, 256, SMEM_FLOATS * 4>>>(
        x, ei, batch, w1, b1, w2, b2, w3, b3, w4, b4,
        w_ih, w_hh, b_ih, b_hh, fc_w, fc_b, h0, c0,
        out, n_nodes, n_edges, npad, nsb);
}

// round 5
// speedup vs baseline: 1.1503x; 1.1503x over previous
#include <cuda_runtime.h>
#include <math.h>

#define MAX_NODES 50000
#define NPAD_CAP 51200
#define MAX_EDGES 800000
#define D 64
#define B 64
#define HL 128
#define SCAN_TILE 1024
#define POOL_CHUNK 1024
#define LAYER_BLOCKS 444
#define SMEM_FLOATS 16512   // wA4 4096 + wB4 4096 + rows 4096 + ts 4096 + 128

// ---------------- scratch (device globals; no allocation) ----------------
__device__ __align__(16) int g_counts[NPAD_CAP];
__device__ __align__(16) int g_offs[NPAD_CAP];
__device__ __align__(16) int g_cursor[NPAD_CAP];
__device__ int g_blocksums[64];
__device__ int g_elist[MAX_EDGES];
__device__ __align__(16) float g_h1[MAX_NODES * D];
__device__ __align__(16) float g_h2[MAX_NODES * D];
__device__ __align__(16) float g_sums[B * D];
__device__ float g_cntb[B];

// ---------------- packed f32x2 helpers ----------------
__device__ __forceinline__ void ffma2(unsigned long long& acc,
                                      unsigned long long a, unsigned long long b) {
    asm("fma.rn.f32x2 %0, %1, %2, %3;" : "=l"(acc) : "l"(a), "l"(b), "l"(acc));
}
__device__ __forceinline__ float f32x2_sum(unsigned long long v) {
    float lo = __uint_as_float((unsigned)(v & 0xffffffffull));
    float hi = __uint_as_float((unsigned)(v >> 32));
    return lo + hi;
}

// ---------------- count (+ zero pool accumulators in block 0) ----------------
__global__ void count_kernel(const int* __restrict__ ei, int n_edges,
                             int* __restrict__ counts,
                             float* __restrict__ sums, float* __restrict__ cnt) {
    if (blockIdx.x == 0) {
        for (int i = threadIdx.x; i < B * D; i += blockDim.x) sums[i] = 0.f;
        if (threadIdx.x < B) cnt[threadIdx.x] = 0.f;
    }
    int e = blockIdx.x * blockDim.x + threadIdx.x;
    if (e < n_edges) atomicAdd(&counts[__ldg(ei + n_edges + e)], 1);
}

// ---------------- scanA: per-tile local exclusive scan + tile sum ----------------
__global__ void __launch_bounds__(256) scanA_kernel(
        const int* __restrict__ counts, int* __restrict__ offs,
        int* __restrict__ blocksums) {
    __shared__ int wsum[8];
    int t = threadIdx.x;
    int lane = t & 31, warp = t >> 5;
    int idx = blockIdx.x * SCAN_TILE + t * 4;
    int4 v = *(const int4*)(counts + idx);
    int s = v.x + v.y + v.z + v.w;
    int incl = s;
#pragma unroll
    for (int off = 1; off < 32; off <<= 1) {
        int u = __shfl_up_sync(0xffffffffu, incl, off);
        if (lane >= off) incl += u;
    }
    if (lane == 31) wsum[warp] = incl;
    __syncthreads();
    if (warp == 0) {
        int ws = (lane < 8) ? wsum[lane] : 0;
#pragma unroll
        for (int off = 1; off < 8; off <<= 1) {
            int u = __shfl_up_sync(0xffffffffu, ws, off);
            if (lane >= off) ws += u;
        }
        if (lane < 8) wsum[lane] = ws;
    }
    __syncthreads();
    int wbase = warp ? wsum[warp - 1] : 0;
    int ebase = wbase + incl - s;
    int4 e;
    e.x = ebase; e.y = ebase + v.x; e.z = e.y + v.y; e.w = e.z + v.z;
    *(int4*)(offs + idx) = e;
    if (t == 255) blocksums[blockIdx.x] = wsum[7];
}

// ---------------- scanC: add tile base (self-reduced) ----------------
__global__ void __launch_bounds__(256) scanC_kernel(
        int* __restrict__ offs, int* __restrict__ cursor,
        const int* __restrict__ blocksums) {
    __shared__ int part[2];
    int t = threadIdx.x;
    int lane = t & 31, warp = t >> 5;
    int bid = blockIdx.x;
    int v = (t < bid) ? __ldg(blocksums + t) : 0;   // bid < 64
    if (t < 64) {
#pragma unroll
        for (int off = 16; off; off >>= 1)
            v += __shfl_down_sync(0xffffffffu, v, off);
        if (lane == 0) part[warp] = v;
    }
    __syncthreads();
    int base = part[0] + part[1];
    int idx = bid * SCAN_TILE + t * 4;
    int4 e = *(int4*)(offs + idx);
    e.x += base; e.y += base; e.z += base; e.w += base;
    *(int4*)(offs + idx) = e;
    *(int4*)(cursor + idx) = e;
}

// ---------------- fill edge list (sorted by dst) ----------------
__global__ void fill_kernel(const int* __restrict__ ei, int n_edges,
                            int* __restrict__ cursor, int* __restrict__ elist) {
    int e = blockIdx.x * blockDim.x + threadIdx.x;
    if (e < n_edges) {
        int s = __ldg(ei + e);
        int d = __ldg(ei + n_edges + e);
        int p = atomicAdd(&cursor[d], 1);
        elist[p] = s;
    }
}

// ---------------- fused gather + GIN MLP (one layer per launch) ----------------
// out[i] = relu(relu((xin[i] + sum_{j in N(i)} feat[j]) @ wA.T + bA) @ wB.T + bB)
__global__ void __launch_bounds__(256, 3) layer_kernel(
        const float* __restrict__ feat, const float* __restrict__ xin,
        const float* __restrict__ wA, const float* __restrict__ bA,
        const float* __restrict__ wB, const float* __restrict__ bB,
        float* __restrict__ outbuf, int n) {
    extern __shared__ float smem[];
    float4* wA4 = (float4*)smem;
    float4* wB4 = (float4*)(smem + 4096);
    float* rowsbuf = smem + 8192;
    float* tsbuf = smem + 12288;
    float* bAs = smem + 16384;
    float* bBs = smem + 16448;

    int tid = threadIdx.x, warp = tid >> 5, lane = tid & 31;
    for (int idx = tid; idx < 1024; idx += 256) {
        int j0 = idx & 31, k = (idx >> 5) * 2;
        wA4[idx] = make_float4(wA[j0 * 64 + k], wA[j0 * 64 + k + 1],
                               wA[(j0 + 32) * 64 + k], wA[(j0 + 32) * 64 + k + 1]);
        wB4[idx] = make_float4(wB[j0 * 64 + k], wB[j0 * 64 + k + 1],
                               wB[(j0 + 32) * 64 + k], wB[(j0 + 32) * 64 + k + 1]);
    }
    if (tid < 64) { bAs[tid] = bA[tid]; bBs[tid] = bB[tid]; }
    __syncthreads();

    float* rows = rowsbuf + warp * 512;
    float* ts = tsbuf + warp * 512;
    unsigned rows_a = (unsigned)__cvta_generic_to_shared(rows);
    unsigned ts_a = (unsigned)__cvta_generic_to_shared(ts);
    unsigned wA_a = (unsigned)__cvta_generic_to_shared(wA4);
    unsigned wB_a = (unsigned)__cvta_generic_to_shared(wB4);

    float bAj0 = bAs[lane], bAj1 = bAs[lane + 32];
    float bBj0 = bBs[lane], bBj1 = bBs[lane + 32];

    int ngroups = (n + 7) >> 3;
    for (int g = blockIdx.x * 8 + warp; g < ngroups; g += gridDim.x * 8) {
        int r0 = g * 8;
        // ---- gather 8 rows straight into smem ----
        for (int i = 0; i < 8; i++) {
            int node = r0 + i;
            float2 r = make_float2(0.f, 0.f);
            if (node < n) {
                int start = __ldg(g_offs + node);
                int deg = __ldg(g_counts + node);
                float2 a0 = ((const float2*)(xin + (size_t)node * 64))[lane];
                float2 a1 = make_float2(0.f, 0.f), a2 = make_float2(0.f, 0.f);
                float2 a3 = make_float2(0.f, 0.f), a4 = make_float2(0.f, 0.f);
                float2 a5 = make_float2(0.f, 0.f), a6 = make_float2(0.f, 0.f);
                float2 a7 = make_float2(0.f, 0.f);
                int e = 0;
                for (; e + 7 < deg; e += 8) {
                    int s0 = __ldg(g_elist + start + e);
                    int s1 = __ldg(g_elist + start + e + 1);
                    int s2 = __ldg(g_elist + start + e + 2);
                    int s3 = __ldg(g_elist + start + e + 3);
                    int s4 = __ldg(g_elist + start + e + 4);
                    int s5 = __ldg(g_elist + start + e + 5);
                    int s6 = __ldg(g_elist + start + e + 6);
                    int s7 = __ldg(g_elist + start + e + 7);
                    float2 v0 = ((const float2*)(feat + (size_t)s0 * 64))[lane];
                    float2 v1 = ((const float2*)(feat + (size_t)s1 * 64))[lane];
                    float2 v2 = ((const float2*)(feat + (size_t)s2 * 64))[lane];
                    float2 v3 = ((const float2*)(feat + (size_t)s3 * 64))[lane];
                    float2 v4 = ((const float2*)(feat + (size_t)s4 * 64))[lane];
                    float2 v5 = ((const float2*)(feat + (size_t)s5 * 64))[lane];
                    float2 v6 = ((const float2*)(feat + (size_t)s6 * 64))[lane];
                    float2 v7 = ((const float2*)(feat + (size_t)s7 * 64))[lane];
                    a0.x += v0.x; a0.y += v0.y; a1.x += v1.x; a1.y += v1.y;
                    a2.x += v2.x; a2.y += v2.y; a3.x += v3.x; a3.y += v3.y;
                    a4.x += v4.x; a4.y += v4.y; a5.x += v5.x; a5.y += v5.y;
                    a6.x += v6.x; a6.y += v6.y; a7.x += v7.x; a7.y += v7.y;
                }
                if (e + 3 < deg) {
                    int s0 = __ldg(g_elist + start + e);
                    int s1 = __ldg(g_elist + start + e + 1);
                    int s2 = __ldg(g_elist + start + e + 2);
                    int s3 = __ldg(g_elist + start + e + 3);
                    float2 v0 = ((const float2*)(feat + (size_t)s0 * 64))[lane];
                    float2 v1 = ((const float2*)(feat + (size_t)s1 * 64))[lane];
                    float2 v2 = ((const float2*)(feat + (size_t)s2 * 64))[lane];
                    float2 v3 = ((const float2*)(feat + (size_t)s3 * 64))[lane];
                    a0.x += v0.x; a0.y += v0.y; a1.x += v1.x; a1.y += v1.y;
                    a2.x += v2.x; a2.y += v2.y; a3.x += v3.x; a3.y += v3.y;
                    e += 4;
                }
                for (; e < deg; e++) {
                    int s0 = __ldg(g_elist + start + e);
                    float2 v0 = ((const float2*)(feat + (size_t)s0 * 64))[lane];
                    a0.x += v0.x; a0.y += v0.y;
                }
                r.x = a0.x + a1.x + a2.x + a3.x + a4.x + a5.x + a6.x + a7.x;
                r.y = a0.y + a1.y + a2.y + a3.y + a4.y + a5.y + a6.y + a7.y;
            }
            ((float2*)(rows + i * 64))[lane] = r;
        }
        __syncwarp();

        // ---- phase 1: t = relu(rows @ wA.T + bA) ----
        unsigned long long acc[8][2];
#pragma unroll
        for (int i = 0; i < 8; i++) { acc[i][0] = 0ull; acc[i][1] = 0ull; }
#pragma unroll 4
        for (int k2 = 0; k2 < 32; k2++) {
            unsigned long long w0, w1;
            asm volatile("ld.shared.v2.u64 {%0,%1}, [%2];"
                         : "=l"(w0), "=l"(w1) : "r"(wA_a + (k2 * 32 + lane) * 16));
#pragma unroll
            for (int i = 0; i < 8; i++) {
                unsigned long long h2;
                asm volatile("ld.shared.b64 %0, [%1];"
                             : "=l"(h2) : "r"(rows_a + i * 256 + k2 * 8));
                ffma2(acc[i][0], h2, w0);
                ffma2(acc[i][1], h2, w1);
            }
        }
#pragma unroll
        for (int i = 0; i < 8; i++) {
            ts[i * 64 + lane] = fmaxf(f32x2_sum(acc[i][0]) + bAj0, 0.f);
            ts[i * 64 + lane + 32] = fmaxf(f32x2_sum(acc[i][1]) + bAj1, 0.f);
        }
        __syncwarp();

        // ---- phase 2: out = relu(t @ wB.T + bB) ----
#pragma unroll
        for (int i = 0; i < 8; i++) { acc[i][0] = 0ull; acc[i][1] = 0ull; }
#pragma unroll 4
        for (int k2 = 0; k2 < 32; k2++) {
            unsigned long long w0, w1;
            asm volatile("ld.shared.v2.u64 {%0,%1}, [%2];"
                         : "=l"(w0), "=l"(w1) : "r"(wB_a + (k2 * 32 + lane) * 16));
#pragma unroll
            for (int i = 0; i < 8; i++) {
                unsigned long long h2;
                asm volatile("ld.shared.b64 %0, [%1];"
                             : "=l"(h2) : "r"(ts_a + i * 256 + k2 * 8));
                ffma2(acc[i][0], h2, w0);
                ffma2(acc[i][1], h2, w1);
            }
        }
        int nr = min(8, n - r0);
        for (int i = 0; i < nr; i++) {
            outbuf[(size_t)(r0 + i) * 64 + lane] = fmaxf(f32x2_sum(acc[i][0]) + bBj0, 0.f);
            outbuf[(size_t)(r0 + i) * 64 + lane + 32] = fmaxf(f32x2_sum(acc[i][1]) + bBj1, 0.f);
        }
        __syncwarp();
    }
}

// ---------------- mean-pool over sorted batch ----------------
__global__ void pool_kernel(const float* __restrict__ h,
                            const int* __restrict__ batch, int n,
                            float* __restrict__ sums, float* __restrict__ cnt) {
    int d = threadIdx.x & 63;
    int sub = threadIdx.x >> 6;
    int start = blockIdx.x * POOL_CHUNK + sub;
    int end = min(blockIdx.x * POOL_CHUNK + POOL_CHUNK, n);
    float acc = 0.f, c = 0.f;
    int cur = -1;
    for (int r = start; r < end; r += 4) {
        int b = __ldg(batch + r);
        if (b != cur) {
            if (cur >= 0) {
                atomicAdd(&sums[cur * 64 + d], acc);
                if (d == 0) atomicAdd(&cnt[cur], c);
            }
            cur = b; acc = 0.f; c = 0.f;
        }
        acc += h[(size_t)r * 64 + d];
        c += 1.f;
    }
    if (cur >= 0) {
        atomicAdd(&sums[cur * 64 + d], acc);
        if (d == 0) atomicAdd(&cnt[cur], c);
    }
}

// ---------------- fused gates + LSTM cell + FC + softmax ----------------
__global__ void __launch_bounds__(256) tail_kernel(
        const float* __restrict__ sums, const float* __restrict__ cnt,
        const float* __restrict__ h0, const float* __restrict__ c0,
        const float* __restrict__ w_ih, const float* __restrict__ w_hh,
        const float* __restrict__ b_ih, const float* __restrict__ b_hh,
        const float* __restrict__ fc_w, const float* __restrict__ fc_b,
        float* __restrict__ out) {
    __shared__ float ps[64];
    __shared__ float h0s[128];
    __shared__ float gsm[512];
    __shared__ float h1s[128];
    int b = blockIdx.x;
    int tid = threadIdx.x;
    if (tid < 64) ps[tid] = sums[b * 64 + tid] / fmaxf(cnt[b], 1.f);
    if (tid >= 64 && tid < 192) h0s[tid - 64] = h0[b * 128 + (tid - 64)];
    __syncthreads();
#pragma unroll
    for (int jj = 0; jj < 2; jj++) {
        int j = tid + jj * 256;
        float acc = b_ih[j] + b_hh[j];
        const float4* wi = (const float4*)(w_ih + (size_t)j * 64);
#pragma unroll
        for (int k4 = 0; k4 < 16; k4++) {
            float4 w = __ldg(wi + k4);
            acc += w.x * ps[k4 * 4] + w.y * ps[k4 * 4 + 1]
                 + w.z * ps[k4 * 4 + 2] + w.w * ps[k4 * 4 + 3];
        }
        const float4* wh = (const float4*)(w_hh + (size_t)j * 128);
#pragma unroll
        for (int k4 = 0; k4 < 32; k4++) {
            float4 w = __ldg(wh + k4);
            acc += w.x * h0s[k4 * 4] + w.y * h0s[k4 * 4 + 1]
                 + w.z * h0s[k4 * 4 + 2] + w.w * h0s[k4 * 4 + 3];
        }
        gsm[j] = acc;
    }
    __syncthreads();
    if (tid < 128) {
        float gi = gsm[tid], gf = gsm[128 + tid];
        float gg = gsm[256 + tid], go = gsm[384 + tid];
        float si = 1.f / (1.f + expf(-gi));
        float sf = 1.f / (1.f + expf(-gf));
        float so = 1.f / (1.f + expf(-go));
        float c1 = sf * c0[b * 128 + tid] + si * tanhf(gg);
        float h1v = so * tanhf(c1);
        out[B * 32 + b * 128 + tid] = h1v;
        out[B * 32 + B * 128 + b * 128 + tid] = c1;
        h1s[tid] = h1v;
    }
    __syncthreads();
    if (tid < 32) {
        float acc = fc_b[tid];
        const float4* fw = (const float4*)(fc_w + (size_t)tid * 128);
#pragma unroll
        for (int k4 = 0; k4 < 32; k4++) {
            float4 w = __ldg(fw + k4);
            acc += w.x * h1s[k4 * 4] + w.y * h1s[k4 * 4 + 1]
                 + w.z * h1s[k4 * 4 + 2] + w.w * h1s[k4 * 4 + 3];
        }
        float m = acc;
        for (int off = 16; off; off >>= 1)
            m = fmaxf(m, __shfl_xor_sync(0xffffffffu, m, off));
        float e = expf(acc - m);
        float s = e;
        for (int off = 16; off; off >>= 1)
            s += __shfl_xor_sync(0xffffffffu, s, off);
        out[b * 32 + tid] = e / s;
    }
}

// ---------------- launch ----------------
extern "C" void kernel_launch(void* const* d_in, const int* in_sizes, int n_in,
                              void* d_out, int out_size) {
    const float* x     = (const float*)d_in[0];
    const int*   ei    = (const int*)d_in[1];
    const int*   batch = (const int*)d_in[2];
    const float* w1    = (const float*)d_in[3];
    const float* b1    = (const float*)d_in[4];
    const float* w2    = (const float*)d_in[5];
    const float* b2    = (const float*)d_in[6];
    const float* w3    = (const float*)d_in[7];
    const float* b3    = (const float*)d_in[8];
    const float* w4    = (const float*)d_in[9];
    const float* b4    = (const float*)d_in[10];
    const float* w_ih  = (const float*)d_in[11];
    const float* w_hh  = (const float*)d_in[12];
    const float* b_ih  = (const float*)d_in[13];
    const float* b_hh  = (const float*)d_in[14];
    const float* fc_w  = (const float*)d_in[15];
    const float* fc_b  = (const float*)d_in[16];
    const float* h0    = (const float*)d_in[17];
    const float* c0    = (const float*)d_in[18];
    float* out = (float*)d_out;

    int n_nodes = in_sizes[0] / 64;
    int n_edges = in_sizes[1] / 2;
    int npad = (n_nodes + SCAN_TILE - 1) & ~(SCAN_TILE - 1);
    int nsb = npad / SCAN_TILE;

    int* counts;    cudaGetSymbolAddress((void**)&counts, g_counts);
    int* offs;      cudaGetSymbolAddress((void**)&offs, g_offs);
    int* cursor;    cudaGetSymbolAddress((void**)&cursor, g_cursor);
    int* blocksums; cudaGetSymbolAddress((void**)&blocksums, g_blocksums);
    int* elist;     cudaGetSymbolAddress((void**)&elist, g_elist);
    float* h1;      cudaGetSymbolAddress((void**)&h1, g_h1);
    float* h2;      cudaGetSymbolAddress((void**)&h2, g_h2);
    float* sums;    cudaGetSymbolAddress((void**)&sums, g_sums);
    float* cnt;     cudaGetSymbolAddress((void**)&cnt, g_cntb);

    cudaFuncSetAttribute(layer_kernel, cudaFuncAttributeMaxDynamicSharedMemorySize,
                         SMEM_FLOATS * 4);

    int eb = (n_edges + 255) / 256;
    int pool_blocks = (n_nodes + POOL_CHUNK - 1) / POOL_CHUNK;

    // ---- CSR build ----
    cudaMemsetAsync(counts, 0, npad * sizeof(int));
    count_kernel<<<eb, 256>>>(ei, n_edges, counts, sums, cnt);
    scanA_kernel<<<nsb, 256>>>(counts, offs, blocksums);
    scanC_kernel<<<nsb, 256>>>(offs, cursor, blocksums);
    fill_kernel<<<eb, 256>>>(ei, n_edges, cursor, elist);

    // ---- layers (gather fused into MLP) ----
    layer_kernel<<<LAYER_BLOCKS, 256, SMEM_FLOATS * 4>>>(x, x, w1, b1, w2, b2, h1, n_nodes);
    layer_kernel<<<LAYER_BLOCKS, 256, SMEM_FLOATS * 4>>>(h1, h1, w3, b3, w4, b4, h2, n_nodes);

    // ---- pooling ----
    pool_kernel<<<pool_blocks, 256>>>(h2, batch, n_nodes, sums, cnt);

    // ---- LSTM + FC + softmax ----
    tail_kernel<<<B, 256>>>(sums, cnt, h0, c0, w_ih, w_hh, b_ih, b_hh, fc_w, fc_b, out);
}